// round 9
// baseline (speedup 1.0000x reference)
#include <cuda_runtime.h>

// Problem constants
constexpr int B_ = 8, E_ = 16, H_ = 256, W_ = 256;
constexpr int HW   = H_ * W_;        // 65536
constexpr int NPIX = B_ * HW;        // 524288
constexpr int TPB  = 256;
constexpr int NBLK = NPIX / TPB;     // 2048

// Deterministic fixed-point global accumulator (order-independent integer adds).
__device__ unsigned long long g_acc;   // zeroed at load; reset by last block each run
__device__ unsigned int       g_tick;  // block-completion counter

constexpr double FPSCALE = 4294967296.0;  // 2^32

// Comparator for the sorting network (FMNMX pair, alu pipe).
__device__ __forceinline__ void cmpswap(float& a, float& b) {
    const float lo = fminf(a, b);
    const float hi = fmaxf(a, b);
    a = lo; b = hi;
}

__global__ void __launch_bounds__(TPB, 8)
crps_fused_kernel(const float* __restrict__ fore, const float* __restrict__ obs,
                  float* __restrict__ out) {
    const int g = blockIdx.x * TPB + threadIdx.x;   // pixel id
    const int b = g >> 16;                          // g / HW
    const int p = g & (HW - 1);                     // g % HW

    const float* fb = fore + ((size_t)b * E_) * HW + p;

    // 16 scalar loads with compile-time immediate offsets. MLP=16 per thread.
    float f[E_];
#pragma unroll
    for (int e = 0; e < E_; e++) f[e] = __ldg(fb + e * HW);

    const float o = __ldg(obs + g);

    // term1 numerator: sum_e |f_e - o|   (fma pipe)
    float s1 = 0.f;
#pragma unroll
    for (int e = 0; e < E_; e++) s1 += fabsf(f[e] - o);

    // Green's 60-comparator sorting network for 16 elements (depth 10).
    // L1
    cmpswap(f[0],f[1]);  cmpswap(f[2],f[3]);  cmpswap(f[4],f[5]);  cmpswap(f[6],f[7]);
    cmpswap(f[8],f[9]);  cmpswap(f[10],f[11]);cmpswap(f[12],f[13]);cmpswap(f[14],f[15]);
    // L2
    cmpswap(f[0],f[2]);  cmpswap(f[1],f[3]);  cmpswap(f[4],f[6]);  cmpswap(f[5],f[7]);
    cmpswap(f[8],f[10]); cmpswap(f[9],f[11]); cmpswap(f[12],f[14]);cmpswap(f[13],f[15]);
    // L3
    cmpswap(f[0],f[4]);  cmpswap(f[1],f[5]);  cmpswap(f[2],f[6]);  cmpswap(f[3],f[7]);
    cmpswap(f[8],f[12]); cmpswap(f[9],f[13]); cmpswap(f[10],f[14]);cmpswap(f[11],f[15]);
    // L4
    cmpswap(f[0],f[8]);  cmpswap(f[1],f[9]);  cmpswap(f[2],f[10]); cmpswap(f[3],f[11]);
    cmpswap(f[4],f[12]); cmpswap(f[5],f[13]); cmpswap(f[6],f[14]); cmpswap(f[7],f[15]);
    // L5
    cmpswap(f[5],f[10]); cmpswap(f[6],f[9]);  cmpswap(f[3],f[12]); cmpswap(f[13],f[14]);
    cmpswap(f[7],f[11]); cmpswap(f[1],f[2]);  cmpswap(f[4],f[8]);
    // L6
    cmpswap(f[1],f[4]);  cmpswap(f[7],f[13]); cmpswap(f[2],f[8]);  cmpswap(f[11],f[14]);
    cmpswap(f[5],f[6]);  cmpswap(f[9],f[10]);
    // L7
    cmpswap(f[2],f[4]);  cmpswap(f[11],f[13]);cmpswap(f[3],f[8]);  cmpswap(f[7],f[12]);
    // L8
    cmpswap(f[6],f[8]);  cmpswap(f[10],f[12]);cmpswap(f[3],f[5]);  cmpswap(f[7],f[9]);
    // L9
    cmpswap(f[3],f[4]);  cmpswap(f[5],f[6]);  cmpswap(f[7],f[8]);  cmpswap(f[9],f[10]);
    cmpswap(f[11],f[12]);
    // L10
    cmpswap(f[6],f[7]);  cmpswap(f[8],f[9]);

    // sum_{e<e'} |f_e - f_{e'}| = sum_i (2i - 15) * f_(i)  (ascending)
    float s2 = 0.f;
#pragma unroll
    for (int i = 0; i < E_; i++)
        s2 = fmaf((float)(2 * i - 15), f[i], s2);

    // per-pixel contribution: term1 - 0.5*term2 = s1/16 - s2/256
    const float val = fmaf(s1, 1.0f / 16.0f, -s2 * (1.0f / 256.0f));

    // ---- Deterministic in-kernel reduction ----
    const int lane = threadIdx.x & 31;
    const int wid  = threadIdx.x >> 5;
    float v = val;
#pragma unroll
    for (int off = 16; off > 0; off >>= 1)
        v += __shfl_down_sync(0xffffffffu, v, off);

    __shared__ float ws[TPB / 32];
    if (lane == 0) ws[wid] = v;
    __syncthreads();

    __shared__ bool is_last;
    if (wid == 0) {
        float x = (lane < TPB / 32) ? ws[lane] : 0.f;
#pragma unroll
        for (int off = 4; off > 0; off >>= 1)
            x += __shfl_down_sync(0xffffffffu, x, off);
        if (lane == 0) {
            // Fixed-point -> order-independent (deterministic) global sum.
            const long long q = __double2ll_rn((double)x * FPSCALE);
            atomicAdd(&g_acc, (unsigned long long)q);
            __threadfence();
            const unsigned int tk = atomicAdd(&g_tick, 1u);
            is_last = (tk == (unsigned int)(gridDim.x - 1));
        }
    }
    __syncthreads();

    if (threadIdx.x == 0 && is_last) {
        // All prior block sums are globally visible (ticket acquired after fence).
        const unsigned long long tot = *((volatile unsigned long long*)&g_acc);
        const double s = (double)(long long)tot / FPSCALE;
        out[0] = (float)(s / (double)NPIX);
        // Reset for next graph replay.
        g_acc  = 0ull;
        g_tick = 0u;
        __threadfence();
    }
}

extern "C" void kernel_launch(void* const* d_in, const int* in_sizes, int n_in,
                              void* d_out, int out_size) {
    const float* fore = (const float*)d_in[0];
    const float* obs  = (const float*)d_in[1];
    float* out = (float*)d_out;

    crps_fused_kernel<<<NBLK, TPB>>>(fore, obs, out);
}